// round 10
// baseline (speedup 1.0000x reference)
#include <cuda_runtime.h>
#include <cuda_bf16.h>
#include <cstdint>

#define Bm   32
#define Dm   2560
#define Em   5120
#define RK   160
#define STn  16
#define BE   (Bm*Em)
#define BD   (Bm*Dm)
#define KS_IN   8
#define KS_OUT  16
#define KS_DBC  40

typedef unsigned long long ull;

// -------- scratch ----------
__device__ float g_p_ssm[KS_IN * BE];
__device__ float g_p_mlp[KS_IN * BE];
__device__ float g_xt   [BE];
__device__ float g_res  [BE];
__device__ float g_dbcp [KS_DBC * Bm * 192];
__device__ float g_dbc  [Bm * 192];
__device__ float g_z    [BE];
__device__ float g_p_out[KS_OUT * BD];
// last-block counters (atomicInc wraps -> auto-reset every full pass)
__device__ unsigned int g_ctr_in [2 * 40];
__device__ unsigned int g_ctr_dbc[3];
__device__ unsigned int g_ctr_out[20];

// -------- helpers ----------
__device__ __forceinline__ ull pack2(float x, float y) {
    ull r;
    asm("mov.b64 %0, {%1,%2};" : "=l"(r) : "f"(x), "f"(y));
    return r;
}
__device__ __forceinline__ void fma2(ull& d, ull a, ull b) {
    asm("fma.rn.f32x2 %0, %1, %2, %0;" : "+l"(d) : "l"(a), "l"(b));
}
__device__ __forceinline__ float2 unpack2(ull v) {
    float2 r;
    asm("mov.b64 {%0,%1}, %2;" : "=f"(r.x), "=f"(r.y) : "l"(v));
    return r;
}
__device__ __forceinline__ float silu_f(float v) {
    return v * (1.0f / (1.0f + expf(-v)));
}
__device__ __forceinline__ uint32_t smem_u32(const void* p) {
    uint32_t a;
    asm("{ .reg .u64 t; cvta.to.shared.u64 t, %1; cvt.u32.u64 %0, t; }"
        : "=r"(a) : "l"(p));
    return a;
}
__device__ __forceinline__ void cp_async16(uint32_t dst, const void* src) {
    asm volatile("cp.async.cg.shared.global [%0], [%1], 16;"
                 :: "r"(dst), "l"(src));
}
#define CP_COMMIT()  asm volatile("cp.async.commit_group;")
#define CP_WAIT(n)   asm volatile("cp.async.wait_group %0;" :: "n"(n))

__device__ __forceinline__ uint32_t f2tf(float v) {
    uint32_t u;
    asm("cvt.rna.tf32.f32 %0, %1;" : "=r"(u) : "f"(v));
    return u;
}
__device__ __forceinline__ void mma_tf32(float* d, const uint32_t* a,
                                         uint32_t b0, uint32_t b1) {
    asm volatile(
        "mma.sync.aligned.m16n8k8.row.col.f32.tf32.tf32.f32 "
        "{%0,%1,%2,%3}, {%4,%5,%6,%7}, {%8,%9}, {%0,%1,%2,%3};"
        : "+f"(d[0]), "+f"(d[1]), "+f"(d[2]), "+f"(d[3])
        : "r"(a[0]), "r"(a[1]), "r"(a[2]), "r"(a[3]), "r"(b0), "r"(b1));
}

// returns true (to all threads) if this block is the LAST of `total` arrivals
__device__ __forceinline__ bool last_block(unsigned int* ctr, unsigned int total) {
    __shared__ unsigned int s_last;
    __threadfence();
    if (threadIdx.x == 0)
        s_last = (atomicInc(ctr, total - 1) == total - 1) ? 1u : 0u;
    __syncthreads();
    return s_last != 0;
}

// ---------------------------------------------------------------------------
// tf32 tensor-core 32-row GEMM core: N-tile 128, 128 threads (4 warps).
// W: 3-stage cp.async pipeline, ONE __syncthreads per chunk.
// X: per-chunk tf32 double buffer, LDG prefetched one chunk ahead.
// ---------------------------------------------------------------------------
template <int KPER, int NCOLS, int XSTRIDE>
__device__ __forceinline__
void gemm32_tf2(const float* __restrict__ Xp, const float* __restrict__ W,
                float* __restrict__ part, int n0, int kbase, int ksIdx) {
    __shared__ __align__(16) float    Wfs[3][16][136];
    __shared__ __align__(16) uint32_t Xs[2][32][20];

    const int t    = threadIdx.x;
    const int lane = t & 31;
    const int warp = t >> 5;
    const int g = lane >> 2;
    const int q = lane & 3;
    constexpr int NCH = KPER / 16;

    float d[2][4][4];
#pragma unroll
    for (int m = 0; m < 2; m++)
#pragma unroll
        for (int s = 0; s < 4; s++)
#pragma unroll
            for (int u = 0; u < 4; u++) d[m][s][u] = 0.0f;

    auto issue_w = [&](int c) {
        const int kg = kbase + c * 16;
        const int buf = c % 3;
#pragma unroll
        for (int r = 0; r < 4; r++) {
            int s = t + r * 128, k = s >> 5, seg = s & 31;
            cp_async16(smem_u32(&Wfs[buf][k][seg * 4]),
                       &W[(size_t)(kg + k) * NCOLS + n0 + seg * 4]);
        }
        CP_COMMIT();
    };
    float xreg[4];
    auto load_x = [&](int c) {
        const int kg = kbase + c * 16;
#pragma unroll
        for (int r = 0; r < 4; r++) {
            int i = t + r * 128, b = i >> 4, k = i & 15;
            xreg[r] = Xp[(size_t)b * XSTRIDE + kg + k];
        }
    };
    auto store_x = [&](int c) {
        uint32_t* dst = &Xs[c & 1][0][0];
#pragma unroll
        for (int r = 0; r < 4; r++) {
            int i = t + r * 128, b = i >> 4, k = i & 15;
            dst[b * 20 + k] = f2tf(xreg[r]);
        }
    };

    issue_w(0);
    if (NCH > 1) issue_w(1);
    load_x(0);
    store_x(0);
    if (NCH > 1) load_x(1);

    for (int c = 0; c < NCH; c++) {
        if (c + 1 < NCH) { CP_WAIT(1); } else { CP_WAIT(0); }
        __syncthreads();
        if (c + 2 < NCH) issue_w(c + 2);
        if (c + 1 < NCH) store_x(c + 1);
        if (c + 2 < NCH) load_x(c + 2);

        const int buf = c % 3;
        const uint32_t* Xc = &Xs[c & 1][0][0];
#pragma unroll
        for (int s = 0; s < 2; s++) {
            const int kA = s * 8;
            uint32_t a0[4], a1[4];
            a0[0] = Xc[g * 20 + kA + q];
            a0[1] = Xc[(g + 8) * 20 + kA + q];
            a0[2] = Xc[g * 20 + kA + q + 4];
            a0[3] = Xc[(g + 8) * 20 + kA + q + 4];
            a1[0] = Xc[(16 + g) * 20 + kA + q];
            a1[1] = Xc[(24 + g) * 20 + kA + q];
            a1[2] = Xc[(16 + g) * 20 + kA + q + 4];
            a1[3] = Xc[(24 + g) * 20 + kA + q + 4];
#pragma unroll
            for (int nt = 0; nt < 4; nt++) {
                const int col = warp * 32 + nt * 8 + g;
                uint32_t b0 = f2tf(Wfs[buf][s * 8 + q][col]);
                uint32_t b1 = f2tf(Wfs[buf][s * 8 + q + 4][col]);
                mma_tf32(d[0][nt], a0, b0, b1);
                mma_tf32(d[1][nt], a1, b0, b1);
            }
        }
    }
#pragma unroll
    for (int mt = 0; mt < 2; mt++) {
#pragma unroll
        for (int s = 0; s < 4; s++) {
            int col = n0 + warp * 32 + s * 8 + q * 2;
            size_t r0 = (size_t)(ksIdx * Bm + mt * 16 + g) * NCOLS + col;
            size_t r1 = (size_t)(ksIdx * Bm + mt * 16 + g + 8) * NCOLS + col;
            *reinterpret_cast<float2*>(&part[r0]) =
                make_float2(d[mt][s][0], d[mt][s][1]);
            *reinterpret_cast<float2*>(&part[r1]) =
                make_float2(d[mt][s][2], d[mt][s][3]);
        }
    }
}

// ---------------------------------------------------------------------------
// Fused input GEMMs + last-block (reduce + conv + SiLU).
// grid(40, KS_IN, 2): z=0 -> ssm branch (writes g_xt), z=1 -> mlp (g_res).
// ---------------------------------------------------------------------------
__global__ __launch_bounds__(128)
void gemm_in_kernel(const float* __restrict__ X,
                    const float* __restrict__ W0,
                    const float* __restrict__ W1,
                    const float* __restrict__ conv_w,
                    const float* __restrict__ conv_b,
                    const float* __restrict__ conv_states) {
    const int z = blockIdx.z;
    const float* W = (z == 0) ? W0 : W1;
    float* part    = (z == 0) ? g_p_ssm : g_p_mlp;
    constexpr int KPER = Dm / KS_IN;  // 320
    const int n0 = blockIdx.x * 128;
    gemm32_tf2<KPER, Em, Dm>(X, W, part, n0, blockIdx.y * KPER, blockIdx.y);

    if (!last_block(&g_ctr_in[z * 40 + blockIdx.x], KS_IN)) return;

    const int t = threadIdx.x;
#pragma unroll
    for (int r = 0; r < 8; r++) {
        int i = t + r * 128;           // 1024 float4 slots = 32 rows x 32 seg
        int b = i >> 5, c4 = i & 31;
        int idx = b * Em + n0 + c4 * 4;
        float4 s = make_float4(0.f, 0.f, 0.f, 0.f);
#pragma unroll
        for (int ks = 0; ks < KS_IN; ks++) {
            float4 p = *reinterpret_cast<const float4*>(&part[ks * BE + idx]);
            s.x += p.x; s.y += p.y; s.z += p.z; s.w += p.w;
        }
        if (z == 0) {
            float4 cb = *reinterpret_cast<const float4*>(&conv_b[idx]);
            float4 w0 = *reinterpret_cast<const float4*>(&conv_w[idx]);
            float4 w1 = *reinterpret_cast<const float4*>(&conv_w[idx + BE]);
            float4 w2 = *reinterpret_cast<const float4*>(&conv_w[idx + 2 * BE]);
            float4 w3 = *reinterpret_cast<const float4*>(&conv_w[idx + 3 * BE]);
            float4 s0 = *reinterpret_cast<const float4*>(&conv_states[idx]);
            float4 s1 = *reinterpret_cast<const float4*>(&conv_states[idx + BE]);
            float4 s2 = *reinterpret_cast<const float4*>(&conv_states[idx + 2 * BE]);
            float4 o;
            o.x = silu_f(cb.x + s0.x * w0.x + s1.x * w1.x + s2.x * w2.x + s.x * w3.x);
            o.y = silu_f(cb.y + s0.y * w0.y + s1.y * w1.y + s2.y * w2.y + s.y * w3.y);
            o.z = silu_f(cb.z + s0.z * w0.z + s1.z * w1.z + s2.z * w2.z + s.z * w3.z);
            o.w = silu_f(cb.w + s0.w * w0.w + s1.w * w1.w + s2.w * w2.w + s.w * w3.w);
            *reinterpret_cast<float4*>(&g_xt[idx]) = o;
        } else {
            float4 o = make_float4(silu_f(s.x), silu_f(s.y),
                                   silu_f(s.z), silu_f(s.w));
            *reinterpret_cast<float4*>(&g_res[idx]) = o;
        }
    }
}

// ---------------------------------------------------------------------------
// Output GEMM + last-block reduce -> d_out. grid(20, KS_OUT).
// ---------------------------------------------------------------------------
__global__ __launch_bounds__(128)
void gemm_out_kernel(const float* __restrict__ W, float* __restrict__ out) {
    constexpr int KPER = Em / KS_OUT;  // 320
    const int n0 = blockIdx.x * 128;
    gemm32_tf2<KPER, Dm, Em>(g_z, W, g_p_out, n0, blockIdx.y * KPER, blockIdx.y);

    if (!last_block(&g_ctr_out[blockIdx.x], KS_OUT)) return;

    const int t = threadIdx.x;
#pragma unroll
    for (int r = 0; r < 8; r++) {
        int i = t + r * 128;
        int b = i >> 5, c4 = i & 31;
        int idx = b * Dm + n0 + c4 * 4;
        float4 s = make_float4(0.f, 0.f, 0.f, 0.f);
#pragma unroll
        for (int ks = 0; ks < KS_OUT; ks++) {
            float4 p = *reinterpret_cast<const float4*>(&g_p_out[ks * BD + idx]);
            s.x += p.x; s.y += p.y; s.z += p.z; s.w += p.w;
        }
        *reinterpret_cast<float4*>(&out[idx]) = s;
    }
}

// ---------------------------------------------------------------------------
// dbc GEMM + last-block reduce -> g_dbc. grid(3, KS_DBC).
// ---------------------------------------------------------------------------
__global__ __launch_bounds__(128)
void dbc_gemm_kernel(const float* __restrict__ Wx) {
    __shared__ ull Wsb[2][32][32];
    __shared__ ull Xsb[2][32][33];

    const int t  = threadIdx.x;
    const int n0 = blockIdx.x * 64;
    constexpr int KPER = Em / KS_DBC;  // 128
    constexpr int NCH  = KPER / 32;    // 4
    const int kbase = blockIdx.y * KPER;
    const int cg = t & 15;
    const int rg = t >> 4;
    const int b0 = rg * 4;
    const int qu = cg * 2;

    ull acc[4][2];
#pragma unroll
    for (int j = 0; j < 4; j++) { acc[j][0] = 0ULL; acc[j][1] = 0ULL; }

    float xreg[8];
    {
        const int kg = kbase;
#pragma unroll
        for (int r = 0; r < 4; r++) {
            int s = t + r * 128, row = s >> 4, c16 = s & 15;
            cp_async16(smem_u32(&Wsb[0][row][c16 * 2]),
                       &Wx[(size_t)(kg + row) * 192 + n0 + c16 * 4]);
        }
        CP_COMMIT();
#pragma unroll
        for (int r = 0; r < 8; r++) {
            int i = t + r * 128, b = i >> 5, kk = i & 31;
            xreg[r] = g_xt[b * Em + kg + kk];
        }
    }

    for (int c = 0; c < NCH; c++) {
        const int p = c & 1;
#pragma unroll
        for (int r = 0; r < 8; r++) {
            int i = t + r * 128, b = i >> 5, kk = i & 31;
            Xsb[p][kk][b] = pack2(xreg[r], xreg[r]);
        }
        if (c + 1 < NCH) {
            const int kg = kbase + (c + 1) * 32;
#pragma unroll
            for (int r = 0; r < 4; r++) {
                int s = t + r * 128, row = s >> 4, c16 = s & 15;
                cp_async16(smem_u32(&Wsb[1 - p][row][c16 * 2]),
                           &Wx[(size_t)(kg + row) * 192 + n0 + c16 * 4]);
            }
            CP_COMMIT();
#pragma unroll
            for (int r = 0; r < 8; r++) {
                int i = t + r * 128, b = i >> 5, kk = i & 31;
                xreg[r] = g_xt[b * Em + kg + kk];
            }
            CP_WAIT(1);
        } else {
            CP_WAIT(0);
        }
        __syncthreads();
#pragma unroll
        for (int kk = 0; kk < 32; kk++) {
            ulonglong2 w = *reinterpret_cast<const ulonglong2*>(&Wsb[p][kk][qu]);
            ull xs[4] = {Xsb[p][kk][b0], Xsb[p][kk][b0 + 1],
                         Xsb[p][kk][b0 + 2], Xsb[p][kk][b0 + 3]};
#pragma unroll
            for (int j = 0; j < 4; j++) {
                fma2(acc[j][0], xs[j], w.x);
                fma2(acc[j][1], xs[j], w.y);
            }
        }
        __syncthreads();
    }
#pragma unroll
    for (int j = 0; j < 4; j++) {
        float2 a0 = unpack2(acc[j][0]);
        float2 a1 = unpack2(acc[j][1]);
        *reinterpret_cast<float4*>(
            &g_dbcp[((size_t)blockIdx.y * Bm + b0 + j) * 192 + n0 + cg * 4]) =
            make_float4(a0.x, a0.y, a1.x, a1.y);
    }

    if (!last_block(&g_ctr_dbc[blockIdx.x], KS_DBC)) return;

#pragma unroll
    for (int r = 0; r < 4; r++) {
        int i = t + r * 128;               // 512 float4 = 32 rows x 16 segs
        int b = i >> 4, c4 = i & 15;
        int o = b * 192 + n0 + c4 * 4;
        float4 s = make_float4(0.f, 0.f, 0.f, 0.f);
#pragma unroll
        for (int ks = 0; ks < KS_DBC; ks++) {
            float4 p = *reinterpret_cast<const float4*>(&g_dbcp[ks * Bm * 192 + o]);
            s.x += p.x; s.y += p.y; s.z += p.z; s.w += p.w;
        }
        *reinterpret_cast<float4*>(&g_dbc[o]) = s;
    }
}

// ---------------------------------------------------------------------------
__global__ __launch_bounds__(256)
void ssm_kernel(const float* __restrict__ W_dt,
                const float* __restrict__ dt_bias,
                const float* __restrict__ A_log,
                const float* __restrict__ Dv,
                const float* __restrict__ h) {
    int gid = blockIdx.x * 256 + threadIdx.x;  // [0, 16*Em)
    int e  = gid % Em;
    int b0 = (gid / Em) * 2;

    float dt0 = 0.0f, dt1 = 0.0f;
#pragma unroll 8
    for (int k = 0; k < RK; k++) {
        float wd = W_dt[(size_t)k * Em + e];
        dt0 += g_dbc[b0 * 192 + k] * wd;
        dt1 += g_dbc[(b0 + 1) * 192 + k] * wd;
    }

    float bias = dt_bias[e];
    float dval = Dv[e];
    float An[STn];
#pragma unroll
    for (int n = 0; n < STn; n++) An[n] = -expf(A_log[(size_t)e * STn + n]);

    float dts[2] = {dt0, dt1};
#pragma unroll
    for (int j = 0; j < 2; j++) {
        int b = b0 + j;
        float s = dts[j] + bias;
        float dt = (s > 20.0f) ? s : log1pf(expf(s));
        float xt = g_xt[b * Em + e];
        const float* hb = &h[((size_t)b * Em + e) * STn];
        float y = 0.0f;
#pragma unroll
        for (int n = 0; n < STn; n++) {
            float Bv = g_dbc[b * 192 + 160 + n];
            float Cv = g_dbc[b * 192 + 176 + n];
            float dA = expf(dt * An[n]);
            float hn = hb[n] * dA + dt * Bv * xt;
            y += hn * Cv;
        }
        y += dval * xt;
        g_z[b * Em + e] = y * g_res[b * Em + e];
    }
}

// ---------------------------------------------------------------------------
extern "C" void kernel_launch(void* const* d_in, const int* in_sizes, int n_in,
                              void* d_out, int out_size) {
    const float* x        = (const float*)d_in[0];
    const float* W_in_ssm = (const float*)d_in[1];
    const float* W_in_mlp = (const float*)d_in[2];
    const float* W_out    = (const float*)d_in[3];
    const float* conv_w   = (const float*)d_in[4];
    const float* conv_b   = (const float*)d_in[5];
    const float* conv_st  = (const float*)d_in[6];
    const float* Wx       = (const float*)d_in[7];
    const float* W_dt     = (const float*)d_in[8];
    const float* dt_bias  = (const float*)d_in[9];
    const float* A_log    = (const float*)d_in[10];
    const float* Dvec     = (const float*)d_in[11];
    const float* h        = (const float*)d_in[12];
    float* out = (float*)d_out;

    gemm_in_kernel<<<dim3(40, KS_IN, 2), 128>>>(x, W_in_ssm, W_in_mlp,
                                                conv_w, conv_b, conv_st);
    dbc_gemm_kernel<<<dim3(3, KS_DBC), 128>>>(Wx);
    ssm_kernel<<<320, 256>>>(W_dt, dt_bias, A_log, Dvec, h);
    gemm_out_kernel<<<dim3(20, KS_OUT), 128>>>(W_out, out);
}

// round 11
// speedup vs baseline: 1.1815x; 1.1815x over previous
#include <cuda_runtime.h>
#include <cuda_bf16.h>
#include <cstdint>

#define Bm   32
#define Dm   2560
#define Em   5120
#define RK   160
#define STn  16
#define BE   (Bm*Em)
#define BD   (Bm*Dm)
#define KS_IN   8
#define KS_OUT  32
#define KS_DBC  40

typedef unsigned long long ull;

// -------- scratch ----------
__device__ float g_p_ssm[KS_IN * BE];
__device__ float g_p_mlp[KS_IN * BE];
__device__ float g_xt   [BE];
__device__ float g_res  [BE];
__device__ float g_dbcp [KS_DBC * Bm * 192];
__device__ float g_dbc  [Bm * 192];
__device__ float g_z    [BE];
__device__ float g_p_out[KS_OUT * BD];

// -------- helpers ----------
__device__ __forceinline__ ull pack2(float x, float y) {
    ull r;
    asm("mov.b64 %0, {%1,%2};" : "=l"(r) : "f"(x), "f"(y));
    return r;
}
__device__ __forceinline__ void fma2(ull& d, ull a, ull b) {
    asm("fma.rn.f32x2 %0, %1, %2, %0;" : "+l"(d) : "l"(a), "l"(b));
}
__device__ __forceinline__ float2 unpack2(ull v) {
    float2 r;
    asm("mov.b64 {%0,%1}, %2;" : "=f"(r.x), "=f"(r.y) : "l"(v));
    return r;
}
__device__ __forceinline__ float silu_f(float v) {
    return v * (1.0f / (1.0f + expf(-v)));
}
__device__ __forceinline__ uint32_t smem_u32(const void* p) {
    uint32_t a;
    asm("{ .reg .u64 t; cvta.to.shared.u64 t, %1; cvt.u32.u64 %0, t; }"
        : "=r"(a) : "l"(p));
    return a;
}
__device__ __forceinline__ void cp_async16(uint32_t dst, const void* src) {
    asm volatile("cp.async.cg.shared.global [%0], [%1], 16;"
                 :: "r"(dst), "l"(src));
}
#define CP_COMMIT()  asm volatile("cp.async.commit_group;")
#define CP_WAIT(n)   asm volatile("cp.async.wait_group %0;" :: "n"(n))

__device__ __forceinline__ uint32_t f2tf(float v) {
    uint32_t u;
    asm("cvt.rna.tf32.f32 %0, %1;" : "=r"(u) : "f"(v));
    return u;
}
__device__ __forceinline__ void mma_tf32(float* d, const uint32_t* a,
                                         uint32_t b0, uint32_t b1) {
    asm volatile(
        "mma.sync.aligned.m16n8k8.row.col.f32.tf32.tf32.f32 "
        "{%0,%1,%2,%3}, {%4,%5,%6,%7}, {%8,%9}, {%0,%1,%2,%3};"
        : "+f"(d[0]), "+f"(d[1]), "+f"(d[2]), "+f"(d[3])
        : "r"(a[0]), "r"(a[1]), "r"(a[2]), "r"(a[3]), "r"(b0), "r"(b1));
}

// ---------------------------------------------------------------------------
// tf32 tensor-core 32-row GEMM: N-tile 128, 128 threads (4 warps).
// W: 3-stage cp.async pipeline, ONE __syncthreads per chunk.
// X: per-chunk tf32 double buffer, LDG prefetched one chunk ahead.
// ---------------------------------------------------------------------------
template <int KPER, int NCOLS, int XSTRIDE>
__device__ __forceinline__
void gemm32_tf2(const float* __restrict__ Xp, const float* __restrict__ W,
                float* __restrict__ part, int n0, int kbase, int ksIdx) {
    __shared__ __align__(16) float    Wfs[3][16][136];
    __shared__ __align__(16) uint32_t Xs[2][32][20];

    const int t    = threadIdx.x;
    const int lane = t & 31;
    const int warp = t >> 5;
    const int g = lane >> 2;
    const int q = lane & 3;
    constexpr int NCH = KPER / 16;

    float d[2][4][4];
#pragma unroll
    for (int m = 0; m < 2; m++)
#pragma unroll
        for (int s = 0; s < 4; s++)
#pragma unroll
            for (int u = 0; u < 4; u++) d[m][s][u] = 0.0f;

    auto issue_w = [&](int c) {
        const int kg = kbase + c * 16;
        const int buf = c % 3;
#pragma unroll
        for (int r = 0; r < 4; r++) {
            int s = t + r * 128, k = s >> 5, seg = s & 31;
            cp_async16(smem_u32(&Wfs[buf][k][seg * 4]),
                       &W[(size_t)(kg + k) * NCOLS + n0 + seg * 4]);
        }
        CP_COMMIT();
    };
    float xreg[4];
    auto load_x = [&](int c) {
        const int kg = kbase + c * 16;
#pragma unroll
        for (int r = 0; r < 4; r++) {
            int i = t + r * 128, b = i >> 4, k = i & 15;
            xreg[r] = Xp[(size_t)b * XSTRIDE + kg + k];
        }
    };
    auto store_x = [&](int c) {
        uint32_t* dst = &Xs[c & 1][0][0];
#pragma unroll
        for (int r = 0; r < 4; r++) {
            int i = t + r * 128, b = i >> 4, k = i & 15;
            dst[b * 20 + k] = f2tf(xreg[r]);
        }
    };

    issue_w(0);
    if (NCH > 1) issue_w(1);
    load_x(0);
    store_x(0);
    if (NCH > 1) load_x(1);

    for (int c = 0; c < NCH; c++) {
        if (c + 1 < NCH) { CP_WAIT(1); } else { CP_WAIT(0); }
        __syncthreads();
        if (c + 2 < NCH) issue_w(c + 2);
        if (c + 1 < NCH) store_x(c + 1);
        if (c + 2 < NCH) load_x(c + 2);

        const int buf = c % 3;
        const uint32_t* Xc = &Xs[c & 1][0][0];
#pragma unroll
        for (int s = 0; s < 2; s++) {
            const int kA = s * 8;
            uint32_t a0[4], a1[4];
            a0[0] = Xc[g * 20 + kA + q];
            a0[1] = Xc[(g + 8) * 20 + kA + q];
            a0[2] = Xc[g * 20 + kA + q + 4];
            a0[3] = Xc[(g + 8) * 20 + kA + q + 4];
            a1[0] = Xc[(16 + g) * 20 + kA + q];
            a1[1] = Xc[(24 + g) * 20 + kA + q];
            a1[2] = Xc[(16 + g) * 20 + kA + q + 4];
            a1[3] = Xc[(24 + g) * 20 + kA + q + 4];
#pragma unroll
            for (int nt = 0; nt < 4; nt++) {
                const int col = warp * 32 + nt * 8 + g;
                uint32_t b0 = f2tf(Wfs[buf][s * 8 + q][col]);
                uint32_t b1 = f2tf(Wfs[buf][s * 8 + q + 4][col]);
                mma_tf32(d[0][nt], a0, b0, b1);
                mma_tf32(d[1][nt], a1, b0, b1);
            }
        }
    }
#pragma unroll
    for (int mt = 0; mt < 2; mt++) {
#pragma unroll
        for (int s = 0; s < 4; s++) {
            int col = n0 + warp * 32 + s * 8 + q * 2;
            size_t r0 = (size_t)(ksIdx * Bm + mt * 16 + g) * NCOLS + col;
            size_t r1 = (size_t)(ksIdx * Bm + mt * 16 + g + 8) * NCOLS + col;
            *reinterpret_cast<float2*>(&part[r0]) =
                make_float2(d[mt][s][0], d[mt][s][1]);
            *reinterpret_cast<float2*>(&part[r1]) =
                make_float2(d[mt][s][2], d[mt][s][3]);
        }
    }
}

// Fused input GEMMs: blockIdx.z selects ssm / mlp. grid(40, KS_IN, 2).
__global__ __launch_bounds__(128)
void gemm_in_kernel(const float* __restrict__ X,
                    const float* __restrict__ W0,
                    const float* __restrict__ W1) {
    const float* W = (blockIdx.z == 0) ? W0 : W1;
    float* part    = (blockIdx.z == 0) ? g_p_ssm : g_p_mlp;
    constexpr int KPER = Dm / KS_IN;  // 320
    gemm32_tf2<KPER, Em, Dm>(X, W, part, blockIdx.x * 128,
                             blockIdx.y * KPER, blockIdx.y);
}
__global__ __launch_bounds__(128)
void gemm_out_kernel(const float* __restrict__ W) {
    constexpr int KPER = Em / KS_OUT;  // 160
    gemm32_tf2<KPER, Dm, Em>(g_z, W, g_p_out, blockIdx.x * 128,
                             blockIdx.y * KPER, blockIdx.y);
}

// ---------------------------------------------------------------------------
// dbc GEMM: xt(32,5120) @ Wx(5120,192), f32x2 pipelined.
// ---------------------------------------------------------------------------
__global__ __launch_bounds__(128)
void dbc_gemm_kernel(const float* __restrict__ Wx) {
    __shared__ ull Wsb[2][32][32];
    __shared__ ull Xsb[2][32][33];

    const int t  = threadIdx.x;
    const int n0 = blockIdx.x * 64;
    constexpr int KPER = Em / KS_DBC;  // 128
    constexpr int NCH  = KPER / 32;    // 4
    const int kbase = blockIdx.y * KPER;
    const int cg = t & 15;
    const int rg = t >> 4;
    const int b0 = rg * 4;
    const int qu = cg * 2;

    ull acc[4][2];
#pragma unroll
    for (int j = 0; j < 4; j++) { acc[j][0] = 0ULL; acc[j][1] = 0ULL; }

    float xreg[8];
    {
        const int kg = kbase;
#pragma unroll
        for (int r = 0; r < 4; r++) {
            int s = t + r * 128, row = s >> 4, c16 = s & 15;
            cp_async16(smem_u32(&Wsb[0][row][c16 * 2]),
                       &Wx[(size_t)(kg + row) * 192 + n0 + c16 * 4]);
        }
        CP_COMMIT();
#pragma unroll
        for (int r = 0; r < 8; r++) {
            int i = t + r * 128, b = i >> 5, kk = i & 31;
            xreg[r] = g_xt[b * Em + kg + kk];
        }
    }

    for (int c = 0; c < NCH; c++) {
        const int p = c & 1;
#pragma unroll
        for (int r = 0; r < 8; r++) {
            int i = t + r * 128, b = i >> 5, kk = i & 31;
            Xsb[p][kk][b] = pack2(xreg[r], xreg[r]);
        }
        if (c + 1 < NCH) {
            const int kg = kbase + (c + 1) * 32;
#pragma unroll
            for (int r = 0; r < 4; r++) {
                int s = t + r * 128, row = s >> 4, c16 = s & 15;
                cp_async16(smem_u32(&Wsb[1 - p][row][c16 * 2]),
                           &Wx[(size_t)(kg + row) * 192 + n0 + c16 * 4]);
            }
            CP_COMMIT();
#pragma unroll
            for (int r = 0; r < 8; r++) {
                int i = t + r * 128, b = i >> 5, kk = i & 31;
                xreg[r] = g_xt[b * Em + kg + kk];
            }
            CP_WAIT(1);
        } else {
            CP_WAIT(0);
        }
        __syncthreads();
#pragma unroll
        for (int kk = 0; kk < 32; kk++) {
            ulonglong2 w = *reinterpret_cast<const ulonglong2*>(&Wsb[p][kk][qu]);
            ull xs[4] = {Xsb[p][kk][b0], Xsb[p][kk][b0 + 1],
                         Xsb[p][kk][b0 + 2], Xsb[p][kk][b0 + 3]};
#pragma unroll
            for (int j = 0; j < 4; j++) {
                fma2(acc[j][0], xs[j], w.x);
                fma2(acc[j][1], xs[j], w.y);
            }
        }
        __syncthreads();
    }
#pragma unroll
    for (int j = 0; j < 4; j++) {
        float2 a0 = unpack2(acc[j][0]);
        float2 a1 = unpack2(acc[j][1]);
        *reinterpret_cast<float4*>(
            &g_dbcp[((size_t)blockIdx.y * Bm + b0 + j) * 192 + n0 + cg * 4]) =
            make_float4(a0.x, a0.y, a1.x, a1.y);
    }
}

// ---------------------------------------------------------------------------
__global__ __launch_bounds__(256)
void conv_silu_kernel(const float* __restrict__ conv_w,
                      const float* __restrict__ conv_b,
                      const float* __restrict__ conv_states) {
    int idx = blockIdx.x * 256 + threadIdx.x;
    float xssm = 0.0f, xmlp = 0.0f;
#pragma unroll
    for (int ks = 0; ks < KS_IN; ks++) {
        xssm += g_p_ssm[idx + ks * BE];
        xmlp += g_p_mlp[idx + ks * BE];
    }
    float c = conv_b[idx];
    c += conv_states[idx]          * conv_w[idx];
    c += conv_states[idx + BE]     * conv_w[idx + BE];
    c += conv_states[idx + 2 * BE] * conv_w[idx + 2 * BE];
    c += xssm                      * conv_w[idx + 3 * BE];
    g_xt[idx]  = silu_f(c);
    g_res[idx] = silu_f(xmlp);
}

__global__ __launch_bounds__(128)
void dbc_reduce_kernel() {
    int i = blockIdx.x * 128 + threadIdx.x;  // [0, 6144)
    float s = 0.0f;
#pragma unroll
    for (int ks = 0; ks < KS_DBC; ks++) s += g_dbcp[ks * Bm * 192 + i];
    g_dbc[i] = s;
}

// ---------------------------------------------------------------------------
__global__ __launch_bounds__(256)
void ssm_kernel(const float* __restrict__ W_dt,
                const float* __restrict__ dt_bias,
                const float* __restrict__ A_log,
                const float* __restrict__ Dv,
                const float* __restrict__ h) {
    int gid = blockIdx.x * 256 + threadIdx.x;  // [0, 16*Em)
    int e  = gid % Em;
    int b0 = (gid / Em) * 2;

    float dt0 = 0.0f, dt1 = 0.0f;
#pragma unroll 8
    for (int k = 0; k < RK; k++) {
        float wd = W_dt[(size_t)k * Em + e];
        dt0 += g_dbc[b0 * 192 + k] * wd;
        dt1 += g_dbc[(b0 + 1) * 192 + k] * wd;
    }

    float bias = dt_bias[e];
    float dval = Dv[e];
    float An[STn];
#pragma unroll
    for (int n = 0; n < STn; n++) An[n] = -expf(A_log[(size_t)e * STn + n]);

    float dts[2] = {dt0, dt1};
#pragma unroll
    for (int j = 0; j < 2; j++) {
        int b = b0 + j;
        float s = dts[j] + bias;
        float dt = (s > 20.0f) ? s : log1pf(expf(s));
        float xt = g_xt[b * Em + e];
        const float* hb = &h[((size_t)b * Em + e) * STn];
        float y = 0.0f;
#pragma unroll
        for (int n = 0; n < STn; n++) {
            float Bv = g_dbc[b * 192 + 160 + n];
            float Cv = g_dbc[b * 192 + 176 + n];
            float dA = expf(dt * An[n]);
            float hn = hb[n] * dA + dt * Bv * xt;
            y += hn * Cv;
        }
        y += dval * xt;
        g_z[b * Em + e] = y * g_res[b * Em + e];
    }
}

__global__ void out_reduce_kernel(float* __restrict__ out) {
    int i = blockIdx.x * 256 + threadIdx.x;  // [0, BD)
    float s = 0.0f;
#pragma unroll 8
    for (int ks = 0; ks < KS_OUT; ks++) s += g_p_out[ks * BD + i];
    out[i] = s;
}

// ---------------------------------------------------------------------------
extern "C" void kernel_launch(void* const* d_in, const int* in_sizes, int n_in,
                              void* d_out, int out_size) {
    const float* x        = (const float*)d_in[0];
    const float* W_in_ssm = (const float*)d_in[1];
    const float* W_in_mlp = (const float*)d_in[2];
    const float* W_out    = (const float*)d_in[3];
    const float* conv_w   = (const float*)d_in[4];
    const float* conv_b   = (const float*)d_in[5];
    const float* conv_st  = (const float*)d_in[6];
    const float* Wx       = (const float*)d_in[7];
    const float* W_dt     = (const float*)d_in[8];
    const float* dt_bias  = (const float*)d_in[9];
    const float* A_log    = (const float*)d_in[10];
    const float* Dvec     = (const float*)d_in[11];
    const float* h        = (const float*)d_in[12];
    float* out = (float*)d_out;

    gemm_in_kernel<<<dim3(40, KS_IN, 2), 128>>>(x, W_in_ssm, W_in_mlp);
    conv_silu_kernel<<<BE / 256, 256>>>(conv_w, conv_b, conv_st);
    dbc_gemm_kernel<<<dim3(3, KS_DBC), 128>>>(Wx);
    dbc_reduce_kernel<<<48, 128>>>();
    ssm_kernel<<<320, 256>>>(W_dt, dt_bias, A_log, Dvec, h);
    gemm_out_kernel<<<dim3(20, KS_OUT), 128>>>(W_out);
    out_reduce_kernel<<<BD / 256, 256>>>(out);
}

// round 13
// speedup vs baseline: 1.2194x; 1.0320x over previous
#include <cuda_runtime.h>
#include <cuda_bf16.h>
#include <cstdint>

#define Bm   32
#define Dm   2560
#define Em   5120
#define RK   160
#define STn  16
#define BE   (Bm*Em)
#define BD   (Bm*Dm)
#define KS_IN   8
#define KS_OUT  32
#define KS_DBC  40

typedef unsigned long long ull;

// -------- scratch ----------
__device__ float g_p_ssm[KS_IN * BE];
__device__ float g_p_mlp[KS_IN * BE];
__device__ float g_xt   [BE];
__device__ float g_res  [BE];
__device__ float g_dbcp [KS_DBC * Bm * 192];
__device__ float g_z    [BE];

// -------- helpers ----------
__device__ __forceinline__ ull pack2(float x, float y) {
    ull r;
    asm("mov.b64 %0, {%1,%2};" : "=l"(r) : "f"(x), "f"(y));
    return r;
}
__device__ __forceinline__ void fma2(ull& d, ull a, ull b) {
    asm("fma.rn.f32x2 %0, %1, %2, %0;" : "+l"(d) : "l"(a), "l"(b));
}
__device__ __forceinline__ float2 unpack2(ull v) {
    float2 r;
    asm("mov.b64 {%0,%1}, %2;" : "=f"(r.x), "=f"(r.y) : "l"(v));
    return r;
}
__device__ __forceinline__ float silu_f(float v) {
    return v * (1.0f / (1.0f + expf(-v)));
}
__device__ __forceinline__ uint32_t smem_u32(const void* p) {
    uint32_t a;
    asm("{ .reg .u64 t; cvta.to.shared.u64 t, %1; cvt.u32.u64 %0, t; }"
        : "=r"(a) : "l"(p));
    return a;
}
__device__ __forceinline__ void cp_async16(uint32_t dst, const void* src) {
    asm volatile("cp.async.cg.shared.global [%0], [%1], 16;"
                 :: "r"(dst), "l"(src));
}
#define CP_COMMIT()  asm volatile("cp.async.commit_group;")
#define CP_WAIT(n)   asm volatile("cp.async.wait_group %0;" :: "n"(n))

__device__ __forceinline__ uint32_t f2tf(float v) {
    uint32_t u;
    asm("cvt.rna.tf32.f32 %0, %1;" : "=r"(u) : "f"(v));
    return u;
}
__device__ __forceinline__ void mma_tf32(float* d, const uint32_t* a,
                                         uint32_t b0, uint32_t b1) {
    asm volatile(
        "mma.sync.aligned.m16n8k8.row.col.f32.tf32.tf32.f32 "
        "{%0,%1,%2,%3}, {%4,%5,%6,%7}, {%8,%9}, {%0,%1,%2,%3};"
        : "+f"(d[0]), "+f"(d[1]), "+f"(d[2]), "+f"(d[3])
        : "r"(a[0]), "r"(a[1]), "r"(a[2]), "r"(a[3]), "r"(b0), "r"(b1));
}

// ---------------------------------------------------------------------------
// tf32 tensor-core 32-row GEMM: N-tile 128, 128 threads (4 warps).
// W: 3-stage cp.async pipeline, ONE __syncthreads per chunk.
// X: per-chunk tf32 double buffer, LDG prefetched one chunk ahead.
// EPI = 0: write partials to part[ksIdx]. EPI = 1: atomicAdd into part.
// ---------------------------------------------------------------------------
template <int KPER, int NCOLS, int XSTRIDE, int EPI>
__device__ __forceinline__
void gemm32_tf2(const float* __restrict__ Xp, const float* __restrict__ W,
                float* __restrict__ part, int n0, int kbase, int ksIdx) {
    __shared__ __align__(16) float    Wfs[3][16][136];
    __shared__ __align__(16) uint32_t Xs[2][32][20];

    const int t    = threadIdx.x;
    const int lane = t & 31;
    const int warp = t >> 5;
    const int g = lane >> 2;
    const int q = lane & 3;
    constexpr int NCH = KPER / 16;

    float d[2][4][4];
#pragma unroll
    for (int m = 0; m < 2; m++)
#pragma unroll
        for (int s = 0; s < 4; s++)
#pragma unroll
            for (int u = 0; u < 4; u++) d[m][s][u] = 0.0f;

    auto issue_w = [&](int c) {
        const int kg = kbase + c * 16;
        const int buf = c % 3;
#pragma unroll
        for (int r = 0; r < 4; r++) {
            int s = t + r * 128, k = s >> 5, seg = s & 31;
            cp_async16(smem_u32(&Wfs[buf][k][seg * 4]),
                       &W[(size_t)(kg + k) * NCOLS + n0 + seg * 4]);
        }
        CP_COMMIT();
    };
    float xreg[4];
    auto load_x = [&](int c) {
        const int kg = kbase + c * 16;
#pragma unroll
        for (int r = 0; r < 4; r++) {
            int i = t + r * 128, b = i >> 4, k = i & 15;
            xreg[r] = Xp[(size_t)b * XSTRIDE + kg + k];
        }
    };
    auto store_x = [&](int c) {
        uint32_t* dst = &Xs[c & 1][0][0];
#pragma unroll
        for (int r = 0; r < 4; r++) {
            int i = t + r * 128, b = i >> 4, k = i & 15;
            dst[b * 20 + k] = f2tf(xreg[r]);
        }
    };

    issue_w(0);
    if (NCH > 1) issue_w(1);
    load_x(0);
    store_x(0);
    if (NCH > 1) load_x(1);

    for (int c = 0; c < NCH; c++) {
        if (c + 1 < NCH) { CP_WAIT(1); } else { CP_WAIT(0); }
        __syncthreads();
        if (c + 2 < NCH) issue_w(c + 2);
        if (c + 1 < NCH) store_x(c + 1);
        if (c + 2 < NCH) load_x(c + 2);

        const int buf = c % 3;
        const uint32_t* Xc = &Xs[c & 1][0][0];
#pragma unroll
        for (int s = 0; s < 2; s++) {
            const int kA = s * 8;
            uint32_t a0[4], a1[4];
            a0[0] = Xc[g * 20 + kA + q];
            a0[1] = Xc[(g + 8) * 20 + kA + q];
            a0[2] = Xc[g * 20 + kA + q + 4];
            a0[3] = Xc[(g + 8) * 20 + kA + q + 4];
            a1[0] = Xc[(16 + g) * 20 + kA + q];
            a1[1] = Xc[(24 + g) * 20 + kA + q];
            a1[2] = Xc[(16 + g) * 20 + kA + q + 4];
            a1[3] = Xc[(24 + g) * 20 + kA + q + 4];
#pragma unroll
            for (int nt = 0; nt < 4; nt++) {
                const int col = warp * 32 + nt * 8 + g;
                uint32_t b0 = f2tf(Wfs[buf][s * 8 + q][col]);
                uint32_t b1 = f2tf(Wfs[buf][s * 8 + q + 4][col]);
                mma_tf32(d[0][nt], a0, b0, b1);
                mma_tf32(d[1][nt], a1, b0, b1);
            }
        }
    }
#pragma unroll
    for (int mt = 0; mt < 2; mt++) {
#pragma unroll
        for (int s = 0; s < 4; s++) {
            int col = n0 + warp * 32 + s * 8 + q * 2;
            if (EPI == 0) {
                size_t r0 = (size_t)(ksIdx * Bm + mt * 16 + g) * NCOLS + col;
                size_t r1 = (size_t)(ksIdx * Bm + mt * 16 + g + 8) * NCOLS + col;
                *reinterpret_cast<float2*>(&part[r0]) =
                    make_float2(d[mt][s][0], d[mt][s][1]);
                *reinterpret_cast<float2*>(&part[r1]) =
                    make_float2(d[mt][s][2], d[mt][s][3]);
            } else {
                size_t r0 = (size_t)(mt * 16 + g) * NCOLS + col;
                size_t r1 = (size_t)(mt * 16 + g + 8) * NCOLS + col;
                atomicAdd(&part[r0],     d[mt][s][0]);
                atomicAdd(&part[r0 + 1], d[mt][s][1]);
                atomicAdd(&part[r1],     d[mt][s][2]);
                atomicAdd(&part[r1 + 1], d[mt][s][3]);
            }
        }
    }
}

// Fused input GEMMs: blockIdx.z selects ssm / mlp. grid(40, KS_IN, 2).
__global__ __launch_bounds__(128)
void gemm_in_kernel(const float* __restrict__ X,
                    const float* __restrict__ W0,
                    const float* __restrict__ W1) {
    const float* W = (blockIdx.z == 0) ? W0 : W1;
    float* part    = (blockIdx.z == 0) ? g_p_ssm : g_p_mlp;
    constexpr int KPER = Dm / KS_IN;  // 320
    gemm32_tf2<KPER, Em, Dm, 0>(X, W, part, blockIdx.x * 128,
                                blockIdx.y * KPER, blockIdx.y);
}
// Output GEMM: atomicAdd directly into d_out (zeroed by ssm_kernel).
__global__ __launch_bounds__(128)
void gemm_out_kernel(const float* __restrict__ W, float* __restrict__ out) {
    constexpr int KPER = Em / KS_OUT;  // 160
    gemm32_tf2<KPER, Dm, Em, 1>(g_z, W, out, blockIdx.x * 128,
                                blockIdx.y * KPER, blockIdx.y);
}

// ---------------------------------------------------------------------------
// dbc GEMM: xt(32,5120) @ Wx(5120,192), f32x2 pipelined. grid(3, KS_DBC).
// ---------------------------------------------------------------------------
__global__ __launch_bounds__(128)
void dbc_gemm_kernel(const float* __restrict__ Wx) {
    __shared__ ull Wsb[2][32][32];
    __shared__ ull Xsb[2][32][33];

    const int t  = threadIdx.x;
    const int n0 = blockIdx.x * 64;
    constexpr int KPER = Em / KS_DBC;  // 128
    constexpr int NCH  = KPER / 32;    // 4
    const int kbase = blockIdx.y * KPER;
    const int cg = t & 15;
    const int rg = t >> 4;
    const int b0 = rg * 4;
    const int qu = cg * 2;

    ull acc[4][2];
#pragma unroll
    for (int j = 0; j < 4; j++) { acc[j][0] = 0ULL; acc[j][1] = 0ULL; }

    float xreg[8];
    {
        const int kg = kbase;
#pragma unroll
        for (int r = 0; r < 4; r++) {
            int s = t + r * 128, row = s >> 4, c16 = s & 15;
            cp_async16(smem_u32(&Wsb[0][row][c16 * 2]),
                       &Wx[(size_t)(kg + row) * 192 + n0 + c16 * 4]);
        }
        CP_COMMIT();
#pragma unroll
        for (int r = 0; r < 8; r++) {
            int i = t + r * 128, b = i >> 5, kk = i & 31;
            xreg[r] = g_xt[b * Em + kg + kk];
        }
    }

    for (int c = 0; c < NCH; c++) {
        const int p = c & 1;
#pragma unroll
        for (int r = 0; r < 8; r++) {
            int i = t + r * 128, b = i >> 5, kk = i & 31;
            Xsb[p][kk][b] = pack2(xreg[r], xreg[r]);
        }
        if (c + 1 < NCH) {
            const int kg = kbase + (c + 1) * 32;
#pragma unroll
            for (int r = 0; r < 4; r++) {
                int s = t + r * 128, row = s >> 4, c16 = s & 15;
                cp_async16(smem_u32(&Wsb[1 - p][row][c16 * 2]),
                           &Wx[(size_t)(kg + row) * 192 + n0 + c16 * 4]);
            }
            CP_COMMIT();
#pragma unroll
            for (int r = 0; r < 8; r++) {
                int i = t + r * 128, b = i >> 5, kk = i & 31;
                xreg[r] = g_xt[b * Em + kg + kk];
            }
            CP_WAIT(1);
        } else {
            CP_WAIT(0);
        }
        __syncthreads();
#pragma unroll
        for (int kk = 0; kk < 32; kk++) {
            ulonglong2 w = *reinterpret_cast<const ulonglong2*>(&Wsb[p][kk][qu]);
            ull xs[4] = {Xsb[p][kk][b0], Xsb[p][kk][b0 + 1],
                         Xsb[p][kk][b0 + 2], Xsb[p][kk][b0 + 3]};
#pragma unroll
            for (int j = 0; j < 4; j++) {
                fma2(acc[j][0], xs[j], w.x);
                fma2(acc[j][1], xs[j], w.y);
            }
        }
        __syncthreads();
    }
#pragma unroll
    for (int j = 0; j < 4; j++) {
        float2 a0 = unpack2(acc[j][0]);
        float2 a1 = unpack2(acc[j][1]);
        *reinterpret_cast<float4*>(
            &g_dbcp[((size_t)blockIdx.y * Bm + b0 + j) * 192 + n0 + cg * 4]) =
            make_float4(a0.x, a0.y, a1.x, a1.y);
    }
}

// ---------------------------------------------------------------------------
__global__ __launch_bounds__(256)
void conv_silu_kernel(const float* __restrict__ conv_w,
                      const float* __restrict__ conv_b,
                      const float* __restrict__ conv_states) {
    int idx = blockIdx.x * 256 + threadIdx.x;
    float xssm = 0.0f, xmlp = 0.0f;
#pragma unroll
    for (int ks = 0; ks < KS_IN; ks++) {
        xssm += g_p_ssm[idx + ks * BE];
        xmlp += g_p_mlp[idx + ks * BE];
    }
    float c = conv_b[idx];
    c += conv_states[idx]          * conv_w[idx];
    c += conv_states[idx + BE]     * conv_w[idx + BE];
    c += conv_states[idx + 2 * BE] * conv_w[idx + 2 * BE];
    c += xssm                      * conv_w[idx + 3 * BE];
    g_xt[idx]  = silu_f(c);
    g_res[idx] = silu_f(xmlp);
}

// ---------------------------------------------------------------------------
// ssm: block-local dbc reduce (2 rows -> smem) + dt GEMM + SSM + z = y*res.
// Also zeroes d_out for gemm_out's atomic accumulation (exactly BD threads).
// grid = 320 blocks x 256 threads; each block has uniform b0 (Em % 256 == 0).
// ---------------------------------------------------------------------------
__global__ __launch_bounds__(256)
void ssm_kernel(const float* __restrict__ W_dt,
                const float* __restrict__ dt_bias,
                const float* __restrict__ A_log,
                const float* __restrict__ Dv,
                const float* __restrict__ h,
                float* __restrict__ out) {
    __shared__ float s_dbc[384];
    const int t   = threadIdx.x;
    const int gid = blockIdx.x * 256 + t;   // [0, 16*Em)
    const int e   = gid % Em;
    const int b0  = (gid / Em) * 2;

    out[gid] = 0.0f;   // zero d_out slice for gemm_out atomics

    // reduce this block's two dbc rows from partials (L2-hot) into smem
    for (int idx = t; idx < 384; idx += 256) {
        int row = idx / 192;           // 0 or 1
        int col = idx - row * 192;     // [0,192)  (192 is NOT a pow2 mask!)
        int o = (b0 + row) * 192 + col;
        float s = 0.0f;
#pragma unroll
        for (int ks = 0; ks < KS_DBC; ks++) s += g_dbcp[ks * (Bm * 192) + o];
        s_dbc[idx] = s;
    }
    __syncthreads();

    float dt0 = 0.0f, dt1 = 0.0f;
#pragma unroll 8
    for (int k = 0; k < RK; k++) {
        float wd = W_dt[(size_t)k * Em + e];
        dt0 += s_dbc[k] * wd;
        dt1 += s_dbc[192 + k] * wd;
    }

    float bias = dt_bias[e];
    float dval = Dv[e];
    float An[STn];
#pragma unroll
    for (int n = 0; n < STn; n++) An[n] = -expf(A_log[(size_t)e * STn + n]);

    float dts[2] = {dt0, dt1};
#pragma unroll
    for (int j = 0; j < 2; j++) {
        int b = b0 + j;
        float s = dts[j] + bias;
        float dt = (s > 20.0f) ? s : log1pf(expf(s));
        float xt = g_xt[b * Em + e];
        const float* hb = &h[((size_t)b * Em + e) * STn];
        float y = 0.0f;
#pragma unroll
        for (int n = 0; n < STn; n++) {
            float Bv = s_dbc[j * 192 + 160 + n];
            float Cv = s_dbc[j * 192 + 176 + n];
            float dA = expf(dt * An[n]);
            float hn = hb[n] * dA + dt * Bv * xt;
            y += hn * Cv;
        }
        y += dval * xt;
        g_z[b * Em + e] = y * g_res[b * Em + e];
    }
}

// ---------------------------------------------------------------------------
extern "C" void kernel_launch(void* const* d_in, const int* in_sizes, int n_in,
                              void* d_out, int out_size) {
    const float* x        = (const float*)d_in[0];
    const float* W_in_ssm = (const float*)d_in[1];
    const float* W_in_mlp = (const float*)d_in[2];
    const float* W_out    = (const float*)d_in[3];
    const float* conv_w   = (const float*)d_in[4];
    const float* conv_b   = (const float*)d_in[5];
    const float* conv_st  = (const float*)d_in[6];
    const float* Wx       = (const float*)d_in[7];
    const float* W_dt     = (const float*)d_in[8];
    const float* dt_bias  = (const float*)d_in[9];
    const float* A_log    = (const float*)d_in[10];
    const float* Dvec     = (const float*)d_in[11];
    const float* h        = (const float*)d_in[12];
    float* out = (float*)d_out;

    gemm_in_kernel<<<dim3(40, KS_IN, 2), 128>>>(x, W_in_ssm, W_in_mlp);
    conv_silu_kernel<<<BE / 256, 256>>>(conv_w, conv_b, conv_st);
    dbc_gemm_kernel<<<dim3(3, KS_DBC), 128>>>(Wx);
    ssm_kernel<<<320, 256>>>(W_dt, dt_bias, A_log, Dvec, h, out);
    gemm_out_kernel<<<dim3(20, KS_OUT), 128>>>(W_out, out);
}